// round 5
// baseline (speedup 1.0000x reference)
#include <cuda_runtime.h>
#include <stdint.h>

// Cl(8,0,0): 256 components, 1024 multivectors (4x256), out [3,1024,256].
// gp[i] = sum_j sign(j, j^i) * A[j] * B[j^i]
//   sign(j,k) = (-1)^{popc(j & pp(k))},  pp linear over XOR: pp(k)=pp(j)^pp(i)
//   wedge: j & ~i == 0 ;  inner: (j&i)==0 || (i&~j)==0
// 512-thread blocks: 4 j-slices x 128 i-threads, G=8 batch elems, f32x2 math,
// smem tree reduction. Inner 16-way unroll makes u compile-time so pp(u),
// A-offsets and k-xor const-fold.

#define NCOMP 256
#define G 8
#define BATCH_ELEMS 1024

typedef unsigned long long u64;

#define MUL2(out, a, b) \
    asm("mul.rn.f32x2 %0, %1, %2;" : "=l"(out) : "l"(a), "l"(b))
#define FMA2(out, a, b, c) \
    asm("fma.rn.f32x2 %0, %1, %2, %3;" : "=l"(out) : "l"(a), "l"(b), "l"(c))
#define ADD2(out, a, b) \
    asm("add.rn.f32x2 %0, %1, %2;" : "=l"(out) : "l"(a), "l"(b))

__device__ __forceinline__ u64 pack2(float x) {
    u64 r;
    asm("mov.b64 %0, {%1, %1};" : "=l"(r) : "f"(x));
    return r;
}
__device__ __forceinline__ float2 unpack2(u64 v) {
    float2 f;
    asm("mov.b64 {%0, %1}, %2;" : "=f"(f.x), "=f"(f.y) : "l"(v));
    return f;
}

__host__ __device__ __forceinline__ constexpr unsigned ppf(unsigned v) {
    unsigned x = v << 1;
    x ^= x << 1;
    x ^= x << 2;
    x ^= x << 4;
    return x & 0xffu;
}

// smem: phase 1: sA (256*8 f32 = 8192B) + sB (256*12 f32 = 12288B) = 20480B
//       phase 2 (reduction, after sync): 256 * 13 u64 = 26624B (aliased)
#define SMEM_BYTES 26624
#define RSTRIDE 13

__global__ __launch_bounds__(512, 2) void clifford_kernel(
    const float* __restrict__ A,
    const float* __restrict__ B,
    float* __restrict__ out) {
    __shared__ __align__(16) char smem_raw[SMEM_BYTES];
    float* sA = (float*)smem_raw;             // [j*8 + g]
    float* sB = (float*)(smem_raw + 8192);    // [k*12 + g]

    const int tid = threadIdx.x;              // 0..511
    const int t = tid & 127;
    const int s = tid >> 7;                   // j-slice 0..3
    const int bb = blockIdx.x >> 1;
    const int ih = blockIdx.x & 1;
    const int base = bb * G;
    const int i = ih * 128 + t;

    #pragma unroll
    for (int r = 0; r < (NCOMP * G) / 512; ++r) {
        int idx = r * 512 + tid;
        int j = idx & (NCOMP - 1);
        int g = idx >> 8;
        sA[j * 8 + g] = A[(base + g) * NCOMP + j];
        sB[j * 12 + g] = B[(base + g) * NCOMP + j];
    }
    __syncthreads();

    u64 accg[4], accw[4], acci[4];
    #pragma unroll
    for (int p = 0; p < 4; ++p) { accg[p] = 0ull; accw[p] = 0ull; acci[p] = 0ull; }

    const int noti = ~i;
    const unsigned pp_i = ppf((unsigned)i);
    const int jbase = s * 64;

    #pragma unroll 1
    for (int o = 0; o < 4; ++o) {
        const int jo = jbase + o * 16;                  // bits 4..7
        const unsigned m_o = ppf((unsigned)jo) ^ pp_i;  // pp(jo)^pp(i)
        const int koi = jo ^ i;
        const u64* aob = (const u64*)(sA + jo * 8);     // broadcast rows

        #pragma unroll
        for (int u = 0; u < 16; ++u) {                  // u compile-time
            const int j = jo | u;
            const int k = koi ^ u;
            const unsigned ppk = m_o ^ ppf((unsigned)u);   // = pp(k)
            const unsigned par = (unsigned)__popc(j & (int)ppk) & 1u;
            const float sgn = __int_as_float(0x3f800000u | (par << 31));
            const float wf = ((j & noti) == 0) ? sgn : 0.0f;
            const float nf = (((j & i) == 0) | ((i & ~j) == 0)) ? sgn : 0.0f;
            const u64 s2 = pack2(sgn);
            const u64 w2 = pack2(wf);
            const u64 n2 = pack2(nf);

            const u64* bp = (const u64*)(sB + k * 12);

            #pragma unroll
            for (int p = 0; p < 4; ++p) {
                u64 v;
                MUL2(v, aob[u * 4 + p], bp[p]);
                FMA2(accg[p], v, s2, accg[p]);
                FMA2(accw[p], v, w2, accw[p]);
                FMA2(acci[p], v, n2, acci[p]);
            }
        }
    }

    // Tree reduction across the 4 j-slices (smem aliased over sA/sB)
    __syncthreads();
    u64* red = (u64*)smem_raw;

    if (tid >= 256) {
        u64* dst = red + (tid - 256) * RSTRIDE;
        #pragma unroll
        for (int p = 0; p < 4; ++p) {
            dst[p] = accg[p]; dst[4 + p] = accw[p]; dst[8 + p] = acci[p];
        }
    }
    __syncthreads();
    if (tid < 256) {
        const u64* src = red + tid * RSTRIDE;
        #pragma unroll
        for (int p = 0; p < 4; ++p) {
            ADD2(accg[p], accg[p], src[p]);
            ADD2(accw[p], accw[p], src[4 + p]);
            ADD2(acci[p], acci[p], src[8 + p]);
        }
    }
    __syncthreads();
    if (tid >= 128 && tid < 256) {
        u64* dst = red + (tid - 128) * RSTRIDE;
        #pragma unroll
        for (int p = 0; p < 4; ++p) {
            dst[p] = accg[p]; dst[4 + p] = accw[p]; dst[8 + p] = acci[p];
        }
    }
    __syncthreads();
    if (tid < 128) {
        const u64* src = red + tid * RSTRIDE;
        #pragma unroll
        for (int p = 0; p < 4; ++p) {
            ADD2(accg[p], accg[p], src[p]);
            ADD2(accw[p], accw[p], src[4 + p]);
            ADD2(acci[p], acci[p], src[8 + p]);
        }
        #pragma unroll
        for (int p = 0; p < 4; ++p) {
            float2 g = unpack2(accg[p]);
            float2 w = unpack2(accw[p]);
            float2 n = unpack2(acci[p]);
            const int be0 = base + 2 * p;
            out[(0 * BATCH_ELEMS + be0) * NCOMP + i] = g.x;
            out[(0 * BATCH_ELEMS + be0 + 1) * NCOMP + i] = g.y;
            out[(1 * BATCH_ELEMS + be0) * NCOMP + i] = w.x;
            out[(1 * BATCH_ELEMS + be0 + 1) * NCOMP + i] = w.y;
            out[(2 * BATCH_ELEMS + be0) * NCOMP + i] = n.x;
            out[(2 * BATCH_ELEMS + be0 + 1) * NCOMP + i] = n.y;
        }
    }
}

extern "C" void kernel_launch(void* const* d_in, const int* in_sizes, int n_in,
                              void* d_out, int out_size) {
    const float* A = (const float*)d_in[0];
    const float* B = (const float*)d_in[1];
    float* out = (float*)d_out;
    clifford_kernel<<<(BATCH_ELEMS / G) * 2, 512>>>(A, B, out);
}

// round 6
// speedup vs baseline: 1.4495x; 1.4495x over previous
#include <cuda_runtime.h>
#include <stdint.h>

// Cl(8,0,0): 256 components, 1024 multivectors (4x256), out [3,1024,256].
// gp[i] = sum_j sign(j, j^i) * A[j] * B[j^i]
//   sign(j,k) = (-1)^{popc(j & pp(k))},  pp linear over XOR: pp(k)=pp(j)^pp(i)
//   wedge: j & ~i == 0 ;  inner: (j&i)==0 || (i&~j)==0
// 512-thread blocks: 4 j-slices x 128 i-threads, G=8 batch elems, f32x2 math,
// 128-bit shared loads for both A (broadcast) and B (XOR-coset gather),
// smem tree reduction across slices.

#define NCOMP 256
#define G 8
#define BATCH_ELEMS 1024

typedef unsigned long long u64;

#define MUL2(out, a, b) \
    asm("mul.rn.f32x2 %0, %1, %2;" : "=l"(out) : "l"(a), "l"(b))
#define FMA2(out, a, b, c) \
    asm("fma.rn.f32x2 %0, %1, %2, %3;" : "=l"(out) : "l"(a), "l"(b), "l"(c))
#define ADD2(out, a, b) \
    asm("add.rn.f32x2 %0, %1, %2;" : "=l"(out) : "l"(a), "l"(b))

__device__ __forceinline__ u64 pack2(float x) {
    u64 r;
    asm("mov.b64 %0, {%1, %1};" : "=l"(r) : "f"(x));
    return r;
}
__device__ __forceinline__ float2 unpack2(u64 v) {
    float2 f;
    asm("mov.b64 {%0, %1}, %2;" : "=f"(f.x), "=f"(f.y) : "l"(v));
    return f;
}

__host__ __device__ __forceinline__ constexpr unsigned ppf(unsigned v) {
    unsigned x = v << 1;
    x ^= x << 1;
    x ^= x << 2;
    x ^= x << 4;
    return x & 0xffu;
}

// smem: phase 1: sA (256*8 f32 = 8192B) + sB (256*12 f32 = 12288B) = 20480B
//       phase 2 (reduction, after sync): 256 * 13 u64 = 26624B (aliased)
#define SMEM_BYTES 26624
#define RSTRIDE 13

__global__ __launch_bounds__(512, 2) void clifford_kernel(
    const float* __restrict__ A,
    const float* __restrict__ B,
    float* __restrict__ out) {
    __shared__ __align__(16) char smem_raw[SMEM_BYTES];
    float* sA = (float*)smem_raw;             // [j*8 + g], rows 32B, 16B aligned
    float* sB = (float*)(smem_raw + 8192);    // [k*12 + g], rows 48B, 16B aligned

    const int tid = threadIdx.x;              // 0..511
    const int t = tid & 127;
    const int s = tid >> 7;                   // j-slice 0..3
    const int bb = blockIdx.x >> 1;
    const int ih = blockIdx.x & 1;
    const int base = bb * G;
    const int i = ih * 128 + t;

    #pragma unroll
    for (int r = 0; r < (NCOMP * G) / 512; ++r) {
        int idx = r * 512 + tid;
        int j = idx & (NCOMP - 1);
        int g = idx >> 8;
        sA[j * 8 + g] = A[(base + g) * NCOMP + j];
        sB[j * 12 + g] = B[(base + g) * NCOMP + j];
    }
    __syncthreads();

    u64 accg[4], accw[4], acci[4];
    #pragma unroll
    for (int p = 0; p < 4; ++p) { accg[p] = 0ull; accw[p] = 0ull; acci[p] = 0ull; }

    const int noti = ~i;
    const unsigned pp_i = ppf((unsigned)i);
    const int jbase = s * 64;

    #pragma unroll 1
    for (int o = 0; o < 4; ++o) {
        const int jo = jbase + o * 16;
        const unsigned m_o = ppf((unsigned)jo) ^ pp_i;  // pp(jo)^pp(i)
        const int koi = jo ^ i;

        #pragma unroll
        for (int u = 0; u < 16; ++u) {                  // u compile-time
            const int j = jo | u;
            const int k = koi ^ u;
            const unsigned ppk = m_o ^ ppf((unsigned)u);
            const unsigned par = (unsigned)__popc(j & (int)ppk) & 1u;
            const float sgn = __int_as_float(0x3f800000u | (par << 31));
            const float wf = ((j & noti) == 0) ? sgn : 0.0f;
            const float nf = (((j & i) == 0) | ((i & ~j) == 0)) ? sgn : 0.0f;
            const u64 s2 = pack2(sgn);
            const u64 w2 = pack2(wf);
            const u64 n2 = pack2(nf);

            // 128-bit loads: A broadcast row (32B), B gather row (first 32B of 48B)
            const ulonglong2* ap = (const ulonglong2*)(sA + (jo | u) * 8);
            const ulonglong2* bp = (const ulonglong2*)(sB + k * 12);
            const ulonglong2 a01 = ap[0];
            const ulonglong2 a23 = ap[1];
            const ulonglong2 b01 = bp[0];
            const ulonglong2 b23 = bp[1];

            u64 v0, v1, v2, v3;
            MUL2(v0, a01.x, b01.x);
            MUL2(v1, a01.y, b01.y);
            MUL2(v2, a23.x, b23.x);
            MUL2(v3, a23.y, b23.y);
            FMA2(accg[0], v0, s2, accg[0]);
            FMA2(accg[1], v1, s2, accg[1]);
            FMA2(accg[2], v2, s2, accg[2]);
            FMA2(accg[3], v3, s2, accg[3]);
            FMA2(accw[0], v0, w2, accw[0]);
            FMA2(accw[1], v1, w2, accw[1]);
            FMA2(accw[2], v2, w2, accw[2]);
            FMA2(accw[3], v3, w2, accw[3]);
            FMA2(acci[0], v0, n2, acci[0]);
            FMA2(acci[1], v1, n2, acci[1]);
            FMA2(acci[2], v2, n2, acci[2]);
            FMA2(acci[3], v3, n2, acci[3]);
        }
    }

    // Tree reduction across the 4 j-slices (smem aliased over sA/sB)
    __syncthreads();
    u64* red = (u64*)smem_raw;

    if (tid >= 256) {
        u64* dst = red + (tid - 256) * RSTRIDE;
        #pragma unroll
        for (int p = 0; p < 4; ++p) {
            dst[p] = accg[p]; dst[4 + p] = accw[p]; dst[8 + p] = acci[p];
        }
    }
    __syncthreads();
    if (tid < 256) {
        const u64* src = red + tid * RSTRIDE;
        #pragma unroll
        for (int p = 0; p < 4; ++p) {
            ADD2(accg[p], accg[p], src[p]);
            ADD2(accw[p], accw[p], src[4 + p]);
            ADD2(acci[p], acci[p], src[8 + p]);
        }
    }
    __syncthreads();
    if (tid >= 128 && tid < 256) {
        u64* dst = red + (tid - 128) * RSTRIDE;
        #pragma unroll
        for (int p = 0; p < 4; ++p) {
            dst[p] = accg[p]; dst[4 + p] = accw[p]; dst[8 + p] = acci[p];
        }
    }
    __syncthreads();
    if (tid < 128) {
        const u64* src = red + tid * RSTRIDE;
        #pragma unroll
        for (int p = 0; p < 4; ++p) {
            ADD2(accg[p], accg[p], src[p]);
            ADD2(accw[p], accw[p], src[4 + p]);
            ADD2(acci[p], acci[p], src[8 + p]);
        }
        #pragma unroll
        for (int p = 0; p < 4; ++p) {
            float2 g = unpack2(accg[p]);
            float2 w = unpack2(accw[p]);
            float2 n = unpack2(acci[p]);
            const int be0 = base + 2 * p;
            out[(0 * BATCH_ELEMS + be0) * NCOMP + i] = g.x;
            out[(0 * BATCH_ELEMS + be0 + 1) * NCOMP + i] = g.y;
            out[(1 * BATCH_ELEMS + be0) * NCOMP + i] = w.x;
            out[(1 * BATCH_ELEMS + be0 + 1) * NCOMP + i] = w.y;
            out[(2 * BATCH_ELEMS + be0) * NCOMP + i] = n.x;
            out[(2 * BATCH_ELEMS + be0 + 1) * NCOMP + i] = n.y;
        }
    }
}

extern "C" void kernel_launch(void* const* d_in, const int* in_sizes, int n_in,
                              void* d_out, int out_size) {
    const float* A = (const float*)d_in[0];
    const float* B = (const float*)d_in[1];
    float* out = (float*)d_out;
    clifford_kernel<<<(BATCH_ELEMS / G) * 2, 512>>>(A, B, out);
}